// round 17
// baseline (speedup 1.0000x reference)
#include <cuda_runtime.h>
#include <cuda_bf16.h>
#include <cstdint>
#include <math.h>

// Problem constants
#define HIDDEN  1024
#define NHEADS  16
#define HSIZE   64
#define BATCH   2
#define SEQ     2048
#define BS      (BATCH * SEQ)      // 4096 rows
#define QKVW    (3 * HIDDEN)       // 3072
#define GK      1024               // GEMM K (both projections)
#define NPERSIST 296               // 2 CTAs x 148 SMs

// Scratch (allocation-free rule: __device__ globals)
__device__ float g_attn [ (size_t)BS * HIDDEN ];     // [4096][1024] (tf32-rounded)
__device__ float g_xr   [ (size_t)BS * HIDDEN ];     // x, tf32-rounded
__device__ float g_wqkvT[ (size_t)QKVW * HIDDEN ];   // Wqkv^T (tf32-rounded)
__device__ float g_woT  [ (size_t)HIDDEN * HIDDEN ]; // Wo^T   (tf32-rounded)
// Pre-split bf16 planes, per-head layout: ((b*16+h)*SEQ+s)*64+d
__device__ __nv_bfloat16 g_Qh[(size_t)BS * HIDDEN];
__device__ __nv_bfloat16 g_Ql[(size_t)BS * HIDDEN];
__device__ __nv_bfloat16 g_Kh[(size_t)BS * HIDDEN];
__device__ __nv_bfloat16 g_Kl[(size_t)BS * HIDDEN];
__device__ __nv_bfloat16 g_Vh[(size_t)BS * HIDDEN];
__device__ __nv_bfloat16 g_Vl[(size_t)BS * HIDDEN];

__device__ __forceinline__ uint32_t f2tf32(float x) {
    uint32_t u;
    asm("cvt.rna.tf32.f32 %0, %1;" : "=r"(u) : "f"(x));
    return u;
}

#define MMA_TF32(c, a, b) \
    asm volatile("mma.sync.aligned.m16n8k8.row.col.f32.tf32.tf32.f32 " \
        "{%0,%1,%2,%3}, {%4,%5,%6,%7}, {%8,%9}, {%0,%1,%2,%3};" \
        : "+f"((c)[0]), "+f"((c)[1]), "+f"((c)[2]), "+f"((c)[3]) \
        : "r"((a)[0]), "r"((a)[1]), "r"((a)[2]), "r"((a)[3]), \
          "r"((b)[0]), "r"((b)[1]))

#define MMA_BF16(c, a, b) \
    asm volatile("mma.sync.aligned.m16n8k16.row.col.f32.bf16.bf16.f32 " \
        "{%0,%1,%2,%3}, {%4,%5,%6,%7}, {%8,%9}, {%0,%1,%2,%3};" \
        : "+f"((c)[0]), "+f"((c)[1]), "+f"((c)[2]), "+f"((c)[3]) \
        : "r"((a)[0]), "r"((a)[1]), "r"((a)[2]), "r"((a)[3]), \
          "r"((b)[0]), "r"((b)[1]))

#define LDMX4(r, a) \
    asm volatile("ldmatrix.sync.aligned.m8n8.x4.shared.b16 {%0,%1,%2,%3}, [%4];" \
        : "=r"((r)[0]), "=r"((r)[1]), "=r"((r)[2]), "=r"((r)[3]) : "r"(a))

#define LDMX4T(r, a) \
    asm volatile("ldmatrix.sync.aligned.m8n8.x4.trans.shared.b16 {%0,%1,%2,%3}, [%4];" \
        : "=r"((r)[0]), "=r"((r)[1]), "=r"((r)[2]), "=r"((r)[3]) : "r"(a))

#define CP16(dst, src) \
    asm volatile("cp.async.cg.shared.global [%0], [%1], 16;" \
        :: "r"(dst), "l"(src))
#define CP_COMMIT() asm volatile("cp.async.commit_group;")
#define CP_WAIT1()  asm volatile("cp.async.wait_group 1;")
#define CP_WAIT0()  asm volatile("cp.async.wait_group 0;")

// Split two floats into {hi bf16x2, lo bf16x2}
__device__ __forceinline__ uint2 split2(float x0, float x1) {
    __nv_bfloat162 h = __floats2bfloat162_rn(x0, x1);
    float h0 = __bfloat162float(h.x);
    float h1 = __bfloat162float(h.y);
    __nv_bfloat162 l = __floats2bfloat162_rn(x0 - h0, x1 - h1);
    uint2 r;
    r.x = *reinterpret_cast<uint32_t*>(&h);
    r.y = *reinterpret_cast<uint32_t*>(&l);
    return r;
}

// ---------------------------------------------------------------------------
// Round: out = tf32(in)
// ---------------------------------------------------------------------------
__global__ __launch_bounds__(256) void round_kernel(
    const float* __restrict__ in, float* __restrict__ out)
{
    int i = (blockIdx.x * 256 + threadIdx.x) * 4;
    float4 v = *(const float4*)(in + i);
    float4 o;
    o.x = __uint_as_float(f2tf32(v.x));
    o.y = __uint_as_float(f2tf32(v.y));
    o.z = __uint_as_float(f2tf32(v.z));
    o.w = __uint_as_float(f2tf32(v.w));
    *(float4*)(out + i) = o;
}

// ---------------------------------------------------------------------------
// Transpose + tf32 round: out[C][R] = tf32(in[R][C])
// ---------------------------------------------------------------------------
__global__ __launch_bounds__(256) void transpose_kernel(
    const float* __restrict__ in, float* __restrict__ out, int R, int C)
{
    __shared__ float t[32][33];
    int x  = blockIdx.x * 32 + threadIdx.x;
    int y0 = blockIdx.y * 32;
    #pragma unroll
    for (int i = threadIdx.y; i < 32; i += 8)
        t[i][threadIdx.x] = in[(size_t)(y0 + i) * C + x];
    __syncthreads();
    int ox  = y0 + threadIdx.x;
    int oy0 = blockIdx.x * 32;
    #pragma unroll
    for (int i = threadIdx.y; i < 32; i += 8)
        out[(size_t)(oy0 + i) * R + ox] =
            __uint_as_float(f2tf32(t[threadIdx.x][i]));
}

// ---------------------------------------------------------------------------
// tf32 GEMM v6: persistent CTAs, K-chunk 32, 3-stage cp.async pipeline.
// C = A * BT^T + bias.  mode 0: f32 C+bias.  mode 1: QKV epilogue -> bf16
// hi/lo head planes (Q pre-scaled by 0.125*log2e).
// CTA 128x128, 8 warps (4m x 2n). Each CTA loops tiles with stride gridDim.
// ---------------------------------------------------------------------------
#define GROW 144
#define ABUF 18432                    // one stage of one operand: 128*144
#define OB   55296                    // B base (A[3] first)
#define GEMM_SMEM 110592

__global__ __launch_bounds__(256, 2) void gemm_tf32_mma(
    const float* __restrict__ A, const float* __restrict__ BT,
    const float* __restrict__ bias, float* __restrict__ C, int N, int mode)
{
    extern __shared__ float smem_f[];
    const uint32_t smb = (uint32_t)__cvta_generic_to_shared(smem_f);

    const int tid  = threadIdx.x;
    const int lane = tid & 31;
    const int w    = tid >> 5;
    const int wm   = w & 3;
    const int wn   = w >> 2;
    const int g    = lane >> 2;
    const int t    = lane & 3;

    const int ntiles_n = N >> 7;
    const int numTiles = (BS >> 7) * ntiles_n;

    const int cra = tid >> 3;
    const int cca = (tid & 7) * 16;

    const uint32_t aA = smb + (uint32_t)(wm * 32 + (lane & 15)) * GROW
                      + (lane >> 4) * 16;
    const uint32_t bB = smb + OB
                      + (uint32_t)(wn * 64 + ((lane >> 4) & 1) * 8 + (lane & 7)) * GROW
                      + ((lane >> 3) & 1) * 16;

    const int NCHUNK = GK / 32;   // 32

    for (int tile = blockIdx.x; tile < numTiles; tile += gridDim.x) {
        const int n0 = (tile % ntiles_n) * 128;
        const int m0 = (tile / ntiles_n) * 128;

        __syncthreads();   // all warps done reading SMEM from previous tile

        float c[2][8][4];
        #pragma unroll
        for (int mt = 0; mt < 2; mt++)
            #pragma unroll
            for (int nt = 0; nt < 8; nt++)
                #pragma unroll
                for (int i = 0; i < 4; i++) c[mt][nt][i] = 0.f;

        // Prologue: issue chunks 0,1 into stages 0,1
        #pragma unroll
        for (int s = 0; s < 2; s++) {
            const uint32_t db = s * ABUF;
            const int k0 = s * 32;
            #pragma unroll
            for (int it = 0; it < 4; it++) {
                int r = cra + it * 32;
                CP16(smb + db + r * GROW + cca,
                     A  + (size_t)(m0 + r) * GK + k0 + (cca >> 2));
                CP16(smb + OB + db + r * GROW + cca,
                     BT + (size_t)(n0 + r) * GK + k0 + (cca >> 2));
            }
            CP_COMMIT();
        }

        int st = 0, ist = 2;
        for (int chunk = 0; chunk < NCHUNK; chunk++) {
            const uint32_t ab = st * ABUF;

            if (chunk + 1 < NCHUNK) { CP_WAIT1(); }
            else                    { CP_WAIT0(); }
            __syncthreads();

            if (chunk + 2 < NCHUNK) {
                const int k0 = (chunk + 2) * 32;
                const uint32_t db = ist * ABUF;
                #pragma unroll
                for (int it = 0; it < 4; it++) {
                    int r = cra + it * 32;
                    CP16(smb + db + r * GROW + cca,
                         A  + (size_t)(m0 + r) * GK + k0 + (cca >> 2));
                    CP16(smb + OB + db + r * GROW + cca,
                         BT + (size_t)(n0 + r) * GK + k0 + (cca >> 2));
                }
                CP_COMMIT();
            }

            #pragma unroll
            for (int ks = 0; ks < 4; ks++) {
                uint32_t af[2][4], bf[8][4];
                #pragma unroll
                for (int mt = 0; mt < 2; mt++)
                    LDMX4(af[mt], aA + ab + mt * 16 * GROW + ks * 32);
                #pragma unroll
                for (int p = 0; p < 4; p++)
                    LDMX4(bf[2 * p], bB + ab + p * 16 * GROW + ks * 32);
                #pragma unroll
                for (int mt = 0; mt < 2; mt++)
                    #pragma unroll
                    for (int p = 0; p < 4; p++) {
                        MMA_TF32(c[mt][2 * p],     af[mt], &bf[2 * p][0]);
                        MMA_TF32(c[mt][2 * p + 1], af[mt], &bf[2 * p][2]);
                    }
            }
            st  = (st  == 2) ? 0 : st  + 1;
            ist = (ist == 2) ? 0 : ist + 1;
        }

        if (mode == 1) {
            const int sec = n0 >> 10;
            __nv_bfloat16* ph = (sec == 0) ? g_Qh : (sec == 1) ? g_Kh : g_Vh;
            __nv_bfloat16* pl = (sec == 0) ? g_Ql : (sec == 1) ? g_Kl : g_Vl;
            const float qs = (sec == 0) ? 0.125f * 1.4426950408889634f : 1.0f;
            #pragma unroll
            for (int mt = 0; mt < 2; mt++) {
                const int row = m0 + wm * 32 + mt * 16 + g;
                const int bb = row >> 11, ss = row & 2047;
                #pragma unroll
                for (int nt = 0; nt < 8; nt++) {
                    const int colg = n0 + wn * 64 + nt * 8 + 2 * t;
                    float2 bv = *(const float2*)(bias + colg);
                    const int gc = colg & 1023;
                    const int hh = gc >> 6, d = gc & 63;
                    const size_t dst0 =
                        ((size_t)(bb * NHEADS + hh) * SEQ + ss) * HSIZE + d;
                    const size_t dst1 = dst0 + 8 * HSIZE;
                    uint2 s0 = split2((c[mt][nt][0] + bv.x) * qs,
                                      (c[mt][nt][1] + bv.y) * qs);
                    uint2 s1 = split2((c[mt][nt][2] + bv.x) * qs,
                                      (c[mt][nt][3] + bv.y) * qs);
                    *(uint32_t*)(ph + dst0) = s0.x;
                    *(uint32_t*)(pl + dst0) = s0.y;
                    *(uint32_t*)(ph + dst1) = s1.x;
                    *(uint32_t*)(pl + dst1) = s1.y;
                }
            }
        } else {
            #pragma unroll
            for (int mt = 0; mt < 2; mt++) {
                const int row = m0 + wm * 32 + mt * 16 + g;
                #pragma unroll
                for (int nt = 0; nt < 8; nt++) {
                    const int col = n0 + wn * 64 + nt * 8 + t * 2;
                    float2 bv = *(const float2*)(bias + col);
                    float2 o0 = { c[mt][nt][0] + bv.x, c[mt][nt][1] + bv.y };
                    float2 o1 = { c[mt][nt][2] + bv.x, c[mt][nt][3] + bv.y };
                    *(float2*)(C + (size_t)row * N + col)       = o0;
                    *(float2*)(C + (size_t)(row + 8) * N + col) = o1;
                }
            }
        }
    }
}

// ---------------------------------------------------------------------------
// Flash attention — persistent CTAs. bf16x3 m16n8k16, pre-split GMEM planes
// (Q in log2-scaled units), cp.async double buffering, register-direct P,
// exp2 softmax. BQ=128, 8 warps; 512 logical tiles over grid 296.
// ---------------------------------------------------------------------------
#define RSTR 144
#define OQH 0
#define OQL 18432
#define OKV0 36864
#define KVBUF 36864
#define ATTN_SMEM 110592

__global__ __launch_bounds__(256, 2) void attn_mma_kernel(
    float* __restrict__ attn_out)
{
    extern __shared__ char sm[];
    const uint32_t smb = (uint32_t)__cvta_generic_to_shared(sm);

    const int tid  = threadIdx.x;
    const int lane = tid & 31;
    const int wm   = tid >> 5;
    const int g    = lane >> 2;
    const int t    = lane & 3;
    const int prow = wm * 16;

    const uint32_t aRow = (uint32_t)(prow + (lane & 15)) * RSTR + (lane >> 4) * 16;
    const uint32_t qA = smb + OQH + aRow;
    const uint32_t kLane = (uint32_t)((((lane >> 4) & 1) * 8) + (lane & 7)) * RSTR
                         + ((lane >> 3) & 1) * 16;
    const uint32_t vLane = (uint32_t)((((lane >> 3) & 1) * 8) + (lane & 7)) * RSTR
                         + ((lane >> 4) & 1) * 16;

    const int cr = tid >> 3;
    const int ccol = (tid & 7) * 16;
    const int csrc = (tid & 7) * 8;

    const int TOT_TILES = (SEQ / 128) * NHEADS * BATCH;   // 512

    for (int tix = blockIdx.x; tix < TOT_TILES; tix += gridDim.x) {
        const int b   = tix >> 8;            // /256
        const int rem = tix & 255;
        const int h   = rem >> 4;
        const int q0  = (rem & 15) * 128;
        const size_t hb = (size_t)(b * NHEADS + h) * SEQ;

        __syncthreads();   // all warps done with previous tile's SMEM

        // Prologue: Q planes + tile-0 KV (one cp.async group)
        #pragma unroll
        for (int it = 0; it < 4; it++) {
            int r = cr + it * 32;
            CP16(smb + OQH + r * RSTR + ccol, g_Qh + (hb + q0 + r) * HSIZE + csrc);
            CP16(smb + OQL + r * RSTR + ccol, g_Ql + (hb + q0 + r) * HSIZE + csrc);
        }
        {
            const uint32_t kvb = smb + OKV0;
            #pragma unroll
            for (int it = 0; it < 2; it++) {
                int r = cr + it * 32;
                size_t src = (hb + r) * HSIZE + csrc;
                uint32_t doff = r * RSTR + ccol;
                CP16(kvb + doff,          g_Kh + src);
                CP16(kvb + 9216 + doff,   g_Kl + src);
                CP16(kvb + 18432 + doff,  g_Vh + src);
                CP16(kvb + 27648 + doff,  g_Vl + src);
            }
        }
        CP_COMMIT();

        float oc[8][4];
        #pragma unroll
        for (int nt = 0; nt < 8; nt++)
            #pragma unroll
            for (int i = 0; i < 4; i++) oc[nt][i] = 0.f;
        float mstat[2] = { -1e30f, -1e30f };
        float lstat[2] = { 0.f, 0.f };

        const int NT = SEQ / 64;
        for (int tile = 0; tile < NT; tile++) {
            const int buf = tile & 1;
            if (tile + 1 < NT) {
                const uint32_t kvb = smb + OKV0 + (buf ^ 1) * KVBUF;
                const int kv1 = (tile + 1) * 64;
                #pragma unroll
                for (int it = 0; it < 2; it++) {
                    int r = cr + it * 32;
                    size_t src = (hb + kv1 + r) * HSIZE + csrc;
                    uint32_t doff = r * RSTR + ccol;
                    CP16(kvb + doff,          g_Kh + src);
                    CP16(kvb + 9216 + doff,   g_Kl + src);
                    CP16(kvb + 18432 + doff,  g_Vh + src);
                    CP16(kvb + 27648 + doff,  g_Vl + src);
                }
                CP_COMMIT();
                CP_WAIT1();
            } else {
                CP_WAIT0();
            }
            __syncthreads();

            const uint32_t kvb = smb + OKV0 + buf * KVBUF;
            const uint32_t kA = kvb + kLane;
            const uint32_t vA = kvb + 18432 + vLane;

            float sc[8][4];
            #pragma unroll
            for (int nt = 0; nt < 8; nt++)
                #pragma unroll
                for (int i = 0; i < 4; i++) sc[nt][i] = 0.f;

            #pragma unroll
            for (int ks = 0; ks < 4; ks++) {
                uint32_t ah[4], al[4];
                LDMX4(ah, qA + ks * 32);
                LDMX4(al, qA + OQL + ks * 32);
                #pragma unroll
                for (int p = 0; p < 4; p++) {
                    uint32_t bh[4], bl[4];
                    LDMX4(bh, kA + p * 2304 + ks * 32);
                    LDMX4(bl, kA + 9216 + p * 2304 + ks * 32);
                    MMA_BF16(sc[2*p],   ah, bh);
                    MMA_BF16(sc[2*p],   al, bh);
                    MMA_BF16(sc[2*p],   ah, bl);
                    MMA_BF16(sc[2*p+1], ah, bh + 2);
                    MMA_BF16(sc[2*p+1], al, bh + 2);
                    MMA_BF16(sc[2*p+1], ah, bl + 2);
                }
            }

            // online softmax in log2 domain
            #pragma unroll
            for (int hf = 0; hf < 2; hf++) {
                const int i0 = hf * 2;
                float rm = -1e30f;
                #pragma unroll
                for (int nt = 0; nt < 8; nt++)
                    rm = fmaxf(rm, fmaxf(sc[nt][i0], sc[nt][i0 + 1]));
                rm = fmaxf(rm, __shfl_xor_sync(0xffffffffu, rm, 1));
                rm = fmaxf(rm, __shfl_xor_sync(0xffffffffu, rm, 2));
                float nm   = fmaxf(mstat[hf], rm);
                float corr = exp2f(mstat[hf] - nm);
                float rs = 0.f;
                #pragma unroll
                for (int nt = 0; nt < 8; nt++) {
                    float p0 = exp2f(sc[nt][i0]     - nm);
                    float p1 = exp2f(sc[nt][i0 + 1] - nm);
                    sc[nt][i0] = p0; sc[nt][i0 + 1] = p1;
                    rs += p0 + p1;
                }
                rs += __shfl_xor_sync(0xffffffffu, rs, 1);
                rs += __shfl_xor_sync(0xffffffffu, rs, 2);
                lstat[hf] = lstat[hf] * corr + rs;
                mstat[hf] = nm;
                #pragma unroll
                for (int nt = 0; nt < 8; nt++) {
                    oc[nt][i0]     *= corr;
                    oc[nt][i0 + 1] *= corr;
                }
            }

            #pragma unroll
            for (int ks = 0; ks < 4; ks++) {
                uint2 u0 = split2(sc[2*ks][0],   sc[2*ks][1]);
                uint2 u1 = split2(sc[2*ks][2],   sc[2*ks][3]);
                uint2 u2 = split2(sc[2*ks+1][0], sc[2*ks+1][1]);
                uint2 u3 = split2(sc[2*ks+1][2], sc[2*ks+1][3]);
                uint32_t ah[4] = { u0.x, u1.x, u2.x, u3.x };
                uint32_t al[4] = { u0.y, u1.y, u2.y, u3.y };
                #pragma unroll
                for (int p = 0; p < 4; p++) {
                    uint32_t bh[4], bl[4];
                    LDMX4T(bh, vA + ks * 2304 + p * 32);
                    LDMX4T(bl, vA + 9216 + ks * 2304 + p * 32);
                    MMA_BF16(oc[2*p],   ah, bh);
                    MMA_BF16(oc[2*p],   al, bh);
                    MMA_BF16(oc[2*p],   ah, bl);
                    MMA_BF16(oc[2*p+1], ah, bh + 2);
                    MMA_BF16(oc[2*p+1], al, bh + 2);
                    MMA_BF16(oc[2*p+1], ah, bl + 2);
                }
            }
            __syncthreads();
        }

        // Epilogue: normalize + store, tf32-rounded
        const float inv0 = 1.0f / lstat[0];
        const float inv1 = 1.0f / lstat[1];
        const size_t r0 = (size_t)(b * SEQ + q0 + prow + g);
        const int col0 = h * HSIZE;
        #pragma unroll
        for (int nt = 0; nt < 8; nt++) {
            const int colw = col0 + nt * 8 + 2 * t;
            float2 o0 = { __uint_as_float(f2tf32(oc[nt][0] * inv0)),
                          __uint_as_float(f2tf32(oc[nt][1] * inv0)) };
            float2 o1 = { __uint_as_float(f2tf32(oc[nt][2] * inv1)),
                          __uint_as_float(f2tf32(oc[nt][3] * inv1)) };
            *(float2*)(attn_out + r0 * HIDDEN + colw)       = o0;
            *(float2*)(attn_out + (r0 + 8) * HIDDEN + colw) = o1;
        }
    }
}

// ---------------------------------------------------------------------------
// Launch
// ---------------------------------------------------------------------------
extern "C" void kernel_launch(void* const* d_in, const int* in_sizes, int n_in,
                              void* d_out, int out_size)
{
    const float* x    = (const float*)d_in[0];
    const float* Wqkv = (const float*)d_in[1];
    const float* bqkv = (const float*)d_in[2];
    const float* Wo   = (const float*)d_in[3];
    const float* bo   = (const float*)d_in[4];
    float* out = (float*)d_out;

    float *attn_p = nullptr, *xr_p = nullptr, *wqkvT_p = nullptr, *woT_p = nullptr;
    cudaGetSymbolAddress((void**)&attn_p,  g_attn);
    cudaGetSymbolAddress((void**)&xr_p,    g_xr);
    cudaGetSymbolAddress((void**)&wqkvT_p, g_wqkvT);
    cudaGetSymbolAddress((void**)&woT_p,   g_woT);

    cudaFuncSetAttribute(attn_mma_kernel,
                         cudaFuncAttributeMaxDynamicSharedMemorySize, ATTN_SMEM);
    cudaFuncSetAttribute(gemm_tf32_mma,
                         cudaFuncAttributeMaxDynamicSharedMemorySize, GEMM_SMEM);

    // 0) Pre-round x; transpose+round weights
    round_kernel<<<(BS * HIDDEN / 4) / 256, 256>>>(x, xr_p);
    transpose_kernel<<<dim3(QKVW / 32, HIDDEN / 32), dim3(32, 8)>>>(
        Wqkv, wqkvT_p, HIDDEN, QKVW);
    transpose_kernel<<<dim3(HIDDEN / 32, HIDDEN / 32), dim3(32, 8)>>>(
        Wo, woT_p, HIDDEN, HIDDEN);

    // 1) QKV projection (persistent, mode 1: fused plane conversion)
    gemm_tf32_mma<<<NPERSIST, 256, GEMM_SMEM>>>(
        xr_p, wqkvT_p, bqkv, nullptr, QKVW, 1);

    // 2) Attention (persistent)
    attn_mma_kernel<<<NPERSIST, 256, ATTN_SMEM>>>(attn_p);

    // 3) Output projection (persistent, mode 0; 256 tiles < grid is fine)
    gemm_tf32_mma<<<256, 256, GEMM_SMEM>>>(
        attn_p, woT_p, bo, out, HIDDEN, 0);
}